// round 14
// baseline (speedup 1.0000x reference)
#include <cuda_runtime.h>
#include <cstdint>

// Problem constants
#define BB 8
#define NN 2048
#define DD 128
#define HH 4
#define DH 32
#define NBH 32          // B*H
#define BN 16384        // B*N

// k3 tensor tiling
#define MT 128          // i rows per CTA
#define KT 64           // j per K-tile
#define NTILES 32       // NN / KT
#define NBP 40          // padded B rows: 32 dh + 1 ones + 7 zero
#define BSPLIT_BYTES (NBP * 128)        // 5120
#define BTILE_BYTES  (2 * BSPLIT_BYTES) // 10240 (hi + lo)

// dynamic smem layout for k3 (A_lo dropped: 38.4 KB total)
#define SM_WHI   0u
#define SM_SB    16384u                  // 2 x 10240
#define SM_RS    36864u
#define SM_RE    37376u
#define SM_RE5   37888u
#define SM_TOTAL 38400u

// ---------------- device scratch ----------------
__device__ float g_h[NBH * NN * DH];          // (b,h,n,dh)
__device__ float g_src[NBH * NN];
__device__ float g_dst[NBH * NN];
__device__ float g_E [NBH * NN];              // exp(src)
__device__ float g_E5[NBH * NN];              // exp(0.2*src)
__device__ float g_F [NBH * NN];              // exp(dst)
__device__ float g_F5[NBH * NN];              // exp(0.2*dst)
__device__ float g_att[BN * DD];              // attention output, (b,n,d)
__device__ __align__(16) unsigned char g_B[NBH * NTILES * BTILE_BYTES]; // ~10.5MB bf16 hi/lo B tiles

// packed f32x2 helpers (k1/k4)
#define FFMA2(accum, a64, b64) \
    asm("fma.rn.f32x2 %0, %1, %2, %0;" : "+l"(accum) : "l"(a64), "l"(b64))

__device__ __forceinline__ unsigned long long dup_f32(float v) {
    unsigned long long r;
    asm("mov.b64 %0, {%1, %1};" : "=l"(r) : "f"(v));
    return r;
}
__device__ __forceinline__ void unpack2(unsigned long long p, float &lo, float &hi) {
    asm("mov.b64 {%0, %1}, %2;" : "=f"(lo), "=f"(hi) : "l"(p));
}
__device__ __forceinline__ void cp16(uint32_t s, const void* g) {
    asm volatile("cp.async.cg.shared.global [%0], [%1], 16;" :: "r"(s), "l"(g));
}
__device__ __forceinline__ uint32_t pack_bf16x2(float lo, float hi) {
    uint32_t r;
    asm("cvt.rn.bf16x2.f32 %0, %1, %2;" : "=r"(r) : "f"(hi), "f"(lo));
    return r;
}
__device__ __forceinline__ void ldsm4(uint32_t* r, uint32_t addr) {
    asm volatile("ldmatrix.sync.aligned.m8n8.x4.shared.b16 {%0,%1,%2,%3}, [%4];"
                 : "=r"(r[0]), "=r"(r[1]), "=r"(r[2]), "=r"(r[3]) : "r"(addr));
}
__device__ __forceinline__ void ldsm2(uint32_t* r, uint32_t addr) {
    asm volatile("ldmatrix.sync.aligned.m8n8.x2.shared.b16 {%0,%1}, [%2];"
                 : "=r"(r[0]), "=r"(r[1]) : "r"(addr));
}
__device__ __forceinline__ void mma_bf16(float* c, const uint32_t* a,
                                         uint32_t b0, uint32_t b1) {
    asm volatile("mma.sync.aligned.m16n8k16.row.col.f32.bf16.bf16.f32 "
                 "{%0,%1,%2,%3}, {%4,%5,%6,%7}, {%8,%9}, {%0,%1,%2,%3};"
                 : "+f"(c[0]), "+f"(c[1]), "+f"(c[2]), "+f"(c[3])
                 : "r"(a[0]), "r"(a[1]), "r"(a[2]), "r"(a[3]), "r"(b0), "r"(b1));
}

// ---------------- Kernel 1: h = x @ W^T, stored (b,h,n,dh) ----------------
__global__ __launch_bounds__(128) void k1_proj(const float* __restrict__ x,
                                               const float* __restrict__ W) {
    __shared__ __align__(16) float sxt[128][20];
    __shared__ float sW[32][129];

    const int t = threadIdx.x;
    const int row0 = blockIdx.x * 16;
    const float* xb = x + (size_t)row0 * DD;
    const uint32_t sxt_addr = (uint32_t)__cvta_generic_to_shared(&sxt[0][0]);

    #pragma unroll
    for (int m = 0; m < 16; ++m) sxt[t][m] = xb[m * DD + t];

    unsigned long long acc[8];
    #pragma unroll
    for (int rp = 0; rp < 8; ++rp) acc[rp] = 0ull;

    for (int kt = 0; kt < DD; kt += 32) {
        __syncthreads();
        #pragma unroll
        for (int m = 0; m < 32; ++m) {
            int lin = t + 128 * m;
            int dp = lin >> 5, k = lin & 31;
            sW[k][dp] = W[dp * DD + kt + k];
        }
        __syncthreads();
        #pragma unroll
        for (int k = 0; k < 32; ++k) {
            unsigned long long wb = dup_f32(sW[k][t]);
            uint32_t ra = sxt_addr + (uint32_t)(kt + k) * 80u;
            unsigned long long x0, x1, x2, x3, x4, x5, x6, x7;
            asm("ld.shared.v2.b64 {%0,%1}, [%2];"    : "=l"(x0), "=l"(x1) : "r"(ra));
            asm("ld.shared.v2.b64 {%0,%1}, [%2+16];" : "=l"(x2), "=l"(x3) : "r"(ra));
            asm("ld.shared.v2.b64 {%0,%1}, [%2+32];" : "=l"(x4), "=l"(x5) : "r"(ra));
            asm("ld.shared.v2.b64 {%0,%1}, [%2+48];" : "=l"(x6), "=l"(x7) : "r"(ra));
            FFMA2(acc[0], x0, wb);
            FFMA2(acc[1], x1, wb);
            FFMA2(acc[2], x2, wb);
            FFMA2(acc[3], x3, wb);
            FFMA2(acc[4], x4, wb);
            FFMA2(acc[5], x5, wb);
            FFMA2(acc[6], x6, wb);
            FFMA2(acc[7], x7, wb);
        }
    }

    const int hh = t >> 5, dh = t & 31;
    #pragma unroll
    for (int rp = 0; rp < 8; ++rp) {
        float a0, a1;
        unpack2(acc[rp], a0, a1);
        int bn = row0 + 2 * rp;
        int b = bn >> 11, n = bn & 2047;
        size_t base = (((size_t)b * HH + hh) * NN + n) * DH + dh;
        g_h[base]      = a0;
        g_h[base + DH] = a1;
    }
}

// ---------------- Kernel 2: src/dst dots + exps ----------------
__global__ __launch_bounds__(256) void k2_srcdst(const float* __restrict__ a_src,
                                                 const float* __restrict__ a_dst) {
    int idx = blockIdx.x * 256 + threadIdx.x;
    int hh = (idx >> 11) & 3;
    const float* hrow = g_h + (size_t)idx * DH;
    const float* as = a_src + hh * DH;
    const float* ad = a_dst + hh * DH;
    float s = 0.f, d = 0.f;
    #pragma unroll
    for (int k = 0; k < DH; ++k) {
        float hv = hrow[k];
        s += hv * as[k];
        d += hv * ad[k];
    }
    g_src[idx] = s;
    g_dst[idx] = d;
    g_E [idx] = __expf(s);
    g_E5[idx] = __expf(0.2f * s);
    g_F [idx] = __expf(d);
    g_F5[idx] = __expf(0.2f * d);
}

// ---------------- Kernel 2b: build swizzled bf16 hi/lo B tiles ----------------
// B tile per (bh, jt): [NBP=40 rows][KT=64 cols] bf16, 128B rows, XOR-swizzled.
// rows 0..31: hT (B[n][k] = h[jt+k][n]); row 32: ones(hi)/zeros(lo); rows 33..39: 0.
__global__ __launch_bounds__(128) void k2b_btiles() {
    __shared__ float sh[64][33];
    const int bh = blockIdx.y, t = blockIdx.x, tid = threadIdx.x;
    const float* hsrc = g_h + ((size_t)bh * NN + t * KT) * DH;

    #pragma unroll
    for (int i = 0; i < 4; ++i) {
        int c = tid + 128 * i;                   // 0..511 float4s
        float4 v = ((const float4*)hsrc)[c];
        int k = c >> 3, n4 = c & 7;
        sh[k][n4 * 4 + 0] = v.x;
        sh[k][n4 * 4 + 1] = v.y;
        sh[k][n4 * 4 + 2] = v.z;
        sh[k][n4 * 4 + 3] = v.w;
    }
    __syncthreads();

    unsigned char* outhi = g_B + (size_t)(bh * NTILES + t) * BTILE_BYTES;
    unsigned char* outlo = outhi + BSPLIT_BYTES;

    #pragma unroll
    for (int i = 0; i < 3; ++i) {
        int ch = tid + 128 * i;                  // 16B chunk id, 0..319
        if (ch < 320) {
            int n = ch >> 3, c8 = ch & 7;
            uint32_t hiw[4], low[4];
            #pragma unroll
            for (int q = 0; q < 4; ++q) {
                float v0, v1;
                if (n < 32)      { v0 = sh[c8 * 8 + 2 * q][n]; v1 = sh[c8 * 8 + 2 * q + 1][n]; }
                else if (n == 32){ v0 = 1.f; v1 = 1.f; }
                else             { v0 = 0.f; v1 = 0.f; }
                uint32_t hw = pack_bf16x2(v0, v1);
                float f0 = __uint_as_float(hw << 16);
                float f1 = __uint_as_float(hw & 0xffff0000u);
                hiw[q] = hw;
                low[q] = (n < 32) ? pack_bf16x2(v0 - f0, v1 - f1) : 0u;
            }
            uint32_t off = (uint32_t)(n * 128 + (c8 * 16 ^ ((n & 7) << 4)));
            *(uint4*)(outhi + off) = make_uint4(hiw[0], hiw[1], hiw[2], hiw[3]);
            *(uint4*)(outlo + off) = make_uint4(low[0], low[1], low[2], low[3]);
        }
    }
}

// ---------------- Kernel 3: warp-MMA attention, pipelined, 2-term ----------
// grid (16, 32), block 256 (8 warps x 16 rows), 4 CTAs/SM (single wave).
// A = bf16(w) only (no A_lo): softmax weights quantized but self-consistently
// normalized via the ones column. B keeps hi+lo compensation.
__global__ __launch_bounds__(256, 4) void k3_attn_tc(const float* __restrict__ adj) {
    extern __shared__ __align__(128) unsigned char dsm[];

    const int bh = blockIdx.y;
    const int i0 = blockIdx.x * MT;
    const int tid = threadIdx.x;
    const int warp = tid >> 5, lane = tid & 31;

    const uint32_t sb = (uint32_t)__cvta_generic_to_shared(dsm);
    const uint32_t sWhi_a = sb + SM_WHI;
    const uint32_t sB_a   = sb + SM_SB;
    float* sh_rs  = (float*)(dsm + SM_RS);
    float* sh_rE  = (float*)(dsm + SM_RE);
    float* sh_rE5 = (float*)(dsm + SM_RE5);

    if (tid < MT) {
        int gi = bh * NN + i0 + tid;
        sh_rs [tid] = g_src[gi];
        sh_rE [tid] = g_E [gi];
        sh_rE5[tid] = g_E5[gi];
    }

    const int g0 = warp * 16;                 // this warp's 16 i-rows
    const int lr = lane & 7, lq = lane >> 3;
    const uint32_t xr = (uint32_t)lr << 4;    // swizzle term (row&7)<<4

    const uint32_t a_rowoff = (uint32_t)(g0 + lr + ((lq & 1) << 3)) * 128u;
    const uint32_t a_cbx = (uint32_t)(lq >> 1) << 4;
    const uint32_t b_rowadd = (uint32_t)(lr + ((lq >> 1) << 3));
    const uint32_t b_cbx = (uint32_t)(lq & 1) << 4;

    float c[5][4];
    #pragma unroll
    for (int nt = 0; nt < 5; ++nt)
        #pragma unroll
        for (int q = 0; q < 4; ++q) c[nt][q] = 0.f;

    const int jo = bh * NN;
    const unsigned char* gB0 = g_B + (size_t)(bh * NTILES) * BTILE_BYTES;

    // staging: 640 16B chunks per tile
    auto stage = [&](int buf, int t) {
        const unsigned char* gBt = gB0 + (size_t)t * BTILE_BYTES;
        const uint32_t dst = sB_a + (uint32_t)buf * BTILE_BYTES;
        #pragma unroll
        for (int i = 0; i < 3; ++i) {
            int idx = tid + 256 * i;
            if (idx < BTILE_BYTES / 16)
                cp16(dst + (uint32_t)idx * 16u, gBt + idx * 16);
        }
        asm volatile("cp.async.commit_group;");
    };

    stage(0, 0);                               // prefetch tile 0

    for (int t = 0; t < NTILES; ++t) {
        asm volatile("cp.async.wait_group 0;");
        __syncthreads();   // publish sB[t&1] (+ sh_rs on t=0); MMA(t-1) done

        if (t + 1 < NTILES) stage((t + 1) & 1, t + 1);

        // --- gen phase: w(i,j) -> bf16 hi into swizzled A rows (own warp) ---
        {
            const int jt = t * KT;
            const int jg = jo + jt + 2 * lane;
            const float2 dv  = *(const float2*)&g_dst[jg];
            const float2 Fv  = *(const float2*)&g_F [jg];
            const float2 F5v = *(const float2*)&g_F5[jg];
            const float* arow = adj + (size_t)(i0 + g0) * NN + jt + 2 * lane;

            #pragma unroll
            for (int r = 0; r < 16; ++r) {
                const int m = g0 + r;
                const float rs_m  = sh_rs[m];
                const float rE_m  = sh_rE[m];
                const float rE5_m = sh_rE5[m];
                const float2 av = *(const float2*)(arow + (size_t)r * NN);

                float s0 = rs_m + dv.x;
                float c0 = (s0 > 0.f) ? rE_m * Fv.x : rE5_m * F5v.x;
                float w0 = c0 * av.x;
                float s1 = rs_m + dv.y;
                float c1 = (s1 > 0.f) ? rE_m * Fv.y : rE5_m * F5v.y;
                float w1 = c1 * av.y;

                uint32_t hw = pack_bf16x2(w0, w1);
                uint32_t off = (uint32_t)(m * 128 + ((lane * 4) ^ ((m & 7) << 4)));
                asm volatile("st.shared.b32 [%0], %1;" :: "r"(sWhi_a + off), "r"(hw) : "memory");
            }
        }
        __syncwarp();      // gen -> ldmatrix within this warp

        // --- MMA phase: 4 k16-chunks x (2 n16 hi/lo + 1 n8 hi tail) ---
        const uint32_t bb = sB_a + (uint32_t)(t & 1) * BTILE_BYTES;
        #pragma unroll
        for (int ch = 0; ch < 4; ++ch) {
            const uint32_t cba = (uint32_t)(ch * 32) + a_cbx;
            uint32_t ahi[4];
            ldsm4(ahi, sWhi_a + a_rowoff + (cba ^ xr));
            const uint32_t cbb = (uint32_t)(ch * 32) + b_cbx;
            #pragma unroll
            for (int p = 0; p < 2; ++p) {
                const uint32_t baddr = bb + (uint32_t)(p * 16 + b_rowadd) * 128u + (cbb ^ xr);
                uint32_t bh4[4];
                ldsm4(bh4, baddr);
                mma_bf16(c[2 * p],     ahi, bh4[0], bh4[1]);
                mma_bf16(c[2 * p + 1], ahi, bh4[2], bh4[3]);
                uint32_t bl4[4];
                ldsm4(bl4, baddr + BSPLIT_BYTES);
                mma_bf16(c[2 * p],     ahi, bl4[0], bl4[1]);
                mma_bf16(c[2 * p + 1], ahi, bl4[2], bl4[3]);
            }
            // n-tile 4 (rows 32..39: ones col 32; B_lo is zero there -> hi only)
            const uint32_t baddr2 = bb + (uint32_t)(32 + lr) * 128u + (cbb ^ xr);
            uint32_t b2[2];
            ldsm2(b2, baddr2);
            mma_bf16(c[4], ahi, b2[0], b2[1]);
        }
    }

    // --- epilogue: row sums from col 32 (tile 4), normalize, store ---
    const float s_lo = __shfl_sync(0xffffffffu, c[4][0], lane & ~3);
    const float s_hi = __shfl_sync(0xffffffffu, c[4][2], lane & ~3);
    const float r0 = 1.0f / s_lo;
    const float r1 = 1.0f / s_hi;

    const int b = bh >> 2, hh = bh & 3;
    const int ia = i0 + g0 + (lane >> 2);
    float* dst0 = g_att + ((size_t)b * NN + ia) * DD + hh * DH + 2 * (lane & 3);
    float* dst1 = dst0 + 8 * (size_t)DD;   // row ia+8
    #pragma unroll
    for (int nt = 0; nt < 4; ++nt) {
        *(float2*)(dst0 + nt * 8) = make_float2(c[nt][0] * r0, c[nt][1] * r0);
        *(float2*)(dst1 + nt * 8) = make_float2(c[nt][2] * r1, c[nt][3] * r1);
    }
}

// ---------------- Kernel 4: out = att @ Wo^T + bo; y = x + out; LayerNorm ----
__global__ __launch_bounds__(128) void k4_proj_ln(const float* __restrict__ x,
                                                  const float* __restrict__ Wo,
                                                  const float* __restrict__ bo,
                                                  const float* __restrict__ gamma,
                                                  const float* __restrict__ beta,
                                                  float* __restrict__ out) {
    __shared__ __align__(16) float sat[128][20];
    __shared__ float sW[32][129];
    __shared__ float sy[16][128];
    __shared__ float smu[16], srstd[16];

    const int t = threadIdx.x;
    const int row0 = blockIdx.x * 16;
    const float* ab = g_att + (size_t)row0 * DD;
    const uint32_t sat_addr = (uint32_t)__cvta_generic_to_shared(&sat[0][0]);

    #pragma unroll
    for (int m = 0; m < 16; ++m) sat[t][m] = ab[m * DD + t];

    unsigned long long acc[8];
    #pragma unroll
    for (int rp = 0; rp < 8; ++rp) acc[rp] = 0ull;

    for (int kt = 0; kt < DD; kt += 32) {
        __syncthreads();
        #pragma unroll
        for (int m = 0; m < 32; ++m) {
            int lin = t + 128 * m;
            int dp = lin >> 5, k = lin & 31;
            sW[k][dp] = Wo[dp * DD + kt + k];
        }
        __syncthreads();
        #pragma unroll
        for (int k = 0; k < 32; ++k) {
            unsigned long long wb = dup_f32(sW[k][t]);
            uint32_t ra = sat_addr + (uint32_t)(kt + k) * 80u;
            unsigned long long x0, x1, x2, x3, x4, x5, x6, x7;
            asm("ld.shared.v2.b64 {%0,%1}, [%2];"    : "=l"(x0), "=l"(x1) : "r"(ra));
            asm("ld.shared.v2.b64 {%0,%1}, [%2+16];" : "=l"(x2), "=l"(x3) : "r"(ra));
            asm("ld.shared.v2.b64 {%0,%1}, [%2+32];" : "=l"(x4), "=l"(x5) : "r"(ra));
            asm("ld.shared.v2.b64 {%0,%1}, [%2+48];" : "=l"(x6), "=l"(x7) : "r"(ra));
            FFMA2(acc[0], x0, wb);
            FFMA2(acc[1], x1, wb);
            FFMA2(acc[2], x2, wb);
            FFMA2(acc[3], x3, wb);
            FFMA2(acc[4], x4, wb);
            FFMA2(acc[5], x5, wb);
            FFMA2(acc[6], x6, wb);
            FFMA2(acc[7], x7, wb);
        }
    }
    __syncthreads();

    const float bov = bo[t];
    float yv[16];
    #pragma unroll
    for (int rp = 0; rp < 8; ++rp) {
        int r0 = 2 * rp;
        float a0, a1;
        unpack2(acc[rp], a0, a1);
        float y0 = x[(size_t)(row0 + r0) * DD + t]     + a0 + bov;
        float y1 = x[(size_t)(row0 + r0 + 1) * DD + t] + a1 + bov;
        yv[r0] = y0; yv[r0 + 1] = y1;
        sy[r0][t] = y0; sy[r0 + 1][t] = y1;
    }
    __syncthreads();

    {
        int w = t >> 5, lane = t & 31;
        #pragma unroll
        for (int rr = 0; rr < 4; ++rr) {
            int r = w * 4 + rr;
            float s = 0.f, q = 0.f;
            #pragma unroll
            for (int cc = 0; cc < 4; ++cc) {
                float v = sy[r][lane + 32 * cc];
                s += v;
                q += v * v;
            }
            #pragma unroll
            for (int off = 16; off > 0; off >>= 1) {
                s += __shfl_xor_sync(0xffffffffu, s, off);
                q += __shfl_xor_sync(0xffffffffu, q, off);
            }
            if (lane == 0) {
                float mu = s * (1.0f / DD);
                float var = q * (1.0f / DD) - mu * mu;
                smu[r] = mu;
                srstd[r] = rsqrtf(var + 1e-5f);
            }
        }
    }
    __syncthreads();

    const float gv = gamma[t], bev = beta[t];
    #pragma unroll
    for (int r = 0; r < 16; ++r) {
        out[(size_t)(row0 + r) * DD + t] = (yv[r] - smu[r]) * srstd[r] * gv + bev;
    }
}

// ---------------- launch ----------------
extern "C" void kernel_launch(void* const* d_in, const int* in_sizes, int n_in,
                              void* d_out, int out_size) {
    const float* x     = (const float*)d_in[0];
    const float* adj   = (const float*)d_in[1];
    const float* W     = (const float*)d_in[2];
    const float* a_src = (const float*)d_in[3];
    const float* a_dst = (const float*)d_in[4];
    const float* Wo    = (const float*)d_in[5];
    const float* bo    = (const float*)d_in[6];
    const float* gamma = (const float*)d_in[7];
    const float* beta  = (const float*)d_in[8];
    float* out = (float*)d_out;

    cudaFuncSetAttribute(k3_attn_tc, cudaFuncAttributeMaxDynamicSharedMemorySize, SM_TOTAL);

    k1_proj<<<BN / 16, 128>>>(x, W);
    k2_srcdst<<<(NBH * NN) / 256, 256>>>(a_src, a_dst);
    k2b_btiles<<<dim3(NTILES, NBH), 128>>>();
    k3_attn_tc<<<dim3(NN / MT, NBH), 256, SM_TOTAL>>>(adj);
    k4_proj_ln<<<BN / 16, 128>>>(x, Wo, bo, gamma, beta, out);
}

// round 17
// speedup vs baseline: 1.3339x; 1.3339x over previous
#include <cuda_runtime.h>
#include <cstdint>

// Problem constants
#define BB 8
#define NN 2048
#define DD 128
#define HH 4
#define DH 32
#define NBH 32          // B*H
#define BN 16384        // B*N

// k3 tensor tiling
#define MT 128          // i rows per CTA
#define KT 64           // j per K-tile
#define NTILES 32       // NN / KT
#define NBP 40          // padded B rows: 32 dh + 1 ones + 7 zero
#define BSPLIT_BYTES (NBP * 128)        // 5120
#define BTILE_BYTES  (2 * BSPLIT_BYTES) // 10240 (hi + lo)

// dynamic smem layout for k3 (R10 known-good)
#define SM_WHI   0u
#define SM_WLO   16384u
#define SM_SB    32768u                  // 2 x 10240
#define SM_RS    53248u
#define SM_RE    53760u
#define SM_RE5   54272u
#define SM_TOTAL 54784u

// k4a smem layout
#define K4_SM_A   0u        // A hi 16KB @0, A lo @16384; yb (32KB) overlays after MMA
#define K4_SM_B   32768u    // B blob 64KB (hi 32KB, lo 32KB)
#define K4_SM_MU  98304u    // 64 floats
#define K4_SM_RSD 98560u    // 64 floats
#define K4_SM_TOT 98816u

// ---------------- device scratch ----------------
__device__ float g_h[NBH * NN * DH];          // (b,h,n,dh)
__device__ float g_src[NBH * NN];
__device__ float g_dst[NBH * NN];
__device__ float g_E [NBH * NN];              // exp(src)
__device__ float g_E5[NBH * NN];              // exp(0.2*src)
__device__ float g_F [NBH * NN];              // exp(dst)
__device__ float g_F5[NBH * NN];              // exp(0.2*dst)
__device__ float g_att[BN * DD];              // attention output, (b,n,d)
__device__ __align__(16) unsigned char g_B[NBH * NTILES * BTILE_BYTES]; // bf16 hi/lo B tiles
__device__ __align__(16) unsigned char g_Bo[65536];  // Wo blob: hi 32KB, lo 32KB, swizzled

// packed f32x2 helpers (k1)
#define FFMA2(accum, a64, b64) \
    asm("fma.rn.f32x2 %0, %1, %2, %0;" : "+l"(accum) : "l"(a64), "l"(b64))

__device__ __forceinline__ unsigned long long dup_f32(float v) {
    unsigned long long r;
    asm("mov.b64 %0, {%1, %1};" : "=l"(r) : "f"(v));
    return r;
}
__device__ __forceinline__ void unpack2(unsigned long long p, float &lo, float &hi) {
    asm("mov.b64 {%0, %1}, %2;" : "=f"(lo), "=f"(hi) : "l"(p));
}
__device__ __forceinline__ void cp16(uint32_t s, const void* g) {
    asm volatile("cp.async.cg.shared.global [%0], [%1], 16;" :: "r"(s), "l"(g));
}
__device__ __forceinline__ uint32_t pack_bf16x2(float lo, float hi) {
    uint32_t r;
    asm("cvt.rn.bf16x2.f32 %0, %1, %2;" : "=r"(r) : "f"(hi), "f"(lo));
    return r;
}
__device__ __forceinline__ void ldsm4(uint32_t* r, uint32_t addr) {
    asm volatile("ldmatrix.sync.aligned.m8n8.x4.shared.b16 {%0,%1,%2,%3}, [%4];"
                 : "=r"(r[0]), "=r"(r[1]), "=r"(r[2]), "=r"(r[3]) : "r"(addr));
}
__device__ __forceinline__ void ldsm2(uint32_t* r, uint32_t addr) {
    asm volatile("ldmatrix.sync.aligned.m8n8.x2.shared.b16 {%0,%1}, [%2];"
                 : "=r"(r[0]), "=r"(r[1]) : "r"(addr));
}
__device__ __forceinline__ void mma_bf16(float* c, const uint32_t* a,
                                         uint32_t b0, uint32_t b1) {
    asm volatile("mma.sync.aligned.m16n8k16.row.col.f32.bf16.bf16.f32 "
                 "{%0,%1,%2,%3}, {%4,%5,%6,%7}, {%8,%9}, {%0,%1,%2,%3};"
                 : "+f"(c[0]), "+f"(c[1]), "+f"(c[2]), "+f"(c[3])
                 : "r"(a[0]), "r"(a[1]), "r"(a[2]), "r"(a[3]), "r"(b0), "r"(b1));
}

// ---------------- Kernel 1: h = x @ W^T, stored (b,h,n,dh) ----------------
__global__ __launch_bounds__(128) void k1_proj(const float* __restrict__ x,
                                               const float* __restrict__ W) {
    __shared__ __align__(16) float sxt[128][20];
    __shared__ float sW[32][129];

    const int t = threadIdx.x;
    const int row0 = blockIdx.x * 16;
    const float* xb = x + (size_t)row0 * DD;
    const uint32_t sxt_addr = (uint32_t)__cvta_generic_to_shared(&sxt[0][0]);

    #pragma unroll
    for (int m = 0; m < 16; ++m) sxt[t][m] = xb[m * DD + t];

    unsigned long long acc[8];
    #pragma unroll
    for (int rp = 0; rp < 8; ++rp) acc[rp] = 0ull;

    for (int kt = 0; kt < DD; kt += 32) {
        __syncthreads();
        #pragma unroll
        for (int m = 0; m < 32; ++m) {
            int lin = t + 128 * m;
            int dp = lin >> 5, k = lin & 31;
            sW[k][dp] = W[dp * DD + kt + k];
        }
        __syncthreads();
        #pragma unroll
        for (int k = 0; k < 32; ++k) {
            unsigned long long wb = dup_f32(sW[k][t]);
            uint32_t ra = sxt_addr + (uint32_t)(kt + k) * 80u;
            unsigned long long x0, x1, x2, x3, x4, x5, x6, x7;
            asm("ld.shared.v2.b64 {%0,%1}, [%2];"    : "=l"(x0), "=l"(x1) : "r"(ra));
            asm("ld.shared.v2.b64 {%0,%1}, [%2+16];" : "=l"(x2), "=l"(x3) : "r"(ra));
            asm("ld.shared.v2.b64 {%0,%1}, [%2+32];" : "=l"(x4), "=l"(x5) : "r"(ra));
            asm("ld.shared.v2.b64 {%0,%1}, [%2+48];" : "=l"(x6), "=l"(x7) : "r"(ra));
            FFMA2(acc[0], x0, wb);
            FFMA2(acc[1], x1, wb);
            FFMA2(acc[2], x2, wb);
            FFMA2(acc[3], x3, wb);
            FFMA2(acc[4], x4, wb);
            FFMA2(acc[5], x5, wb);
            FFMA2(acc[6], x6, wb);
            FFMA2(acc[7], x7, wb);
        }
    }

    const int hh = t >> 5, dh = t & 31;
    #pragma unroll
    for (int rp = 0; rp < 8; ++rp) {
        float a0, a1;
        unpack2(acc[rp], a0, a1);
        int bn = row0 + 2 * rp;
        int b = bn >> 11, n = bn & 2047;
        size_t base = (((size_t)b * HH + hh) * NN + n) * DH + dh;
        g_h[base]      = a0;
        g_h[base + DH] = a1;
    }
}

// ---------------- Kernel 2: src/dst dots + exps ----------------
__global__ __launch_bounds__(256) void k2_srcdst(const float* __restrict__ a_src,
                                                 const float* __restrict__ a_dst) {
    int idx = blockIdx.x * 256 + threadIdx.x;
    int hh = (idx >> 11) & 3;
    const float* hrow = g_h + (size_t)idx * DH;
    const float* as = a_src + hh * DH;
    const float* ad = a_dst + hh * DH;
    float s = 0.f, d = 0.f;
    #pragma unroll
    for (int k = 0; k < DH; ++k) {
        float hv = hrow[k];
        s += hv * as[k];
        d += hv * ad[k];
    }
    g_src[idx] = s;
    g_dst[idx] = d;
    g_E [idx] = __expf(s);
    g_E5[idx] = __expf(0.2f * s);
    g_F [idx] = __expf(d);
    g_F5[idx] = __expf(0.2f * d);
}

// ---------------- Kernel 2b: build swizzled bf16 hi/lo B tiles (k3) --------
__global__ __launch_bounds__(128) void k2b_btiles() {
    __shared__ float sh[64][33];
    const int bh = blockIdx.y, t = blockIdx.x, tid = threadIdx.x;
    const float* hsrc = g_h + ((size_t)bh * NN + t * KT) * DH;

    #pragma unroll
    for (int i = 0; i < 4; ++i) {
        int c = tid + 128 * i;
        float4 v = ((const float4*)hsrc)[c];
        int k = c >> 3, n4 = c & 7;
        sh[k][n4 * 4 + 0] = v.x;
        sh[k][n4 * 4 + 1] = v.y;
        sh[k][n4 * 4 + 2] = v.z;
        sh[k][n4 * 4 + 3] = v.w;
    }
    __syncthreads();

    unsigned char* outhi = g_B + (size_t)(bh * NTILES + t) * BTILE_BYTES;
    unsigned char* outlo = outhi + BSPLIT_BYTES;

    #pragma unroll
    for (int i = 0; i < 3; ++i) {
        int ch = tid + 128 * i;
        if (ch < 320) {
            int n = ch >> 3, c8 = ch & 7;
            uint32_t hiw[4], low[4];
            #pragma unroll
            for (int q = 0; q < 4; ++q) {
                float v0, v1;
                if (n < 32)      { v0 = sh[c8 * 8 + 2 * q][n]; v1 = sh[c8 * 8 + 2 * q + 1][n]; }
                else if (n == 32){ v0 = 1.f; v1 = 1.f; }
                else             { v0 = 0.f; v1 = 0.f; }
                uint32_t hw = pack_bf16x2(v0, v1);
                float f0 = __uint_as_float(hw << 16);
                float f1 = __uint_as_float(hw & 0xffff0000u);
                hiw[q] = hw;
                low[q] = (n < 32) ? pack_bf16x2(v0 - f0, v1 - f1) : 0u;
            }
            uint32_t off = (uint32_t)(n * 128 + (c8 * 16 ^ ((n & 7) << 4)));
            *(uint4*)(outhi + off) = make_uint4(hiw[0], hiw[1], hiw[2], hiw[3]);
            *(uint4*)(outlo + off) = make_uint4(low[0], low[1], low[2], low[3]);
        }
    }
}

// ---------------- Kernel 2c: Wo -> swizzled bf16 hi/lo blob (for k4a) ------
// Layout: [kb(2)][n(128)][128B], hi at 0, lo at +32768.
__global__ __launch_bounds__(256) void k2c_wo(const float* __restrict__ Wo) {
    const int tid = threadIdx.x;
    #pragma unroll
    for (int i = 0; i < 16; ++i) {
        int lin = tid + 256 * i;              // 4096 float4s
        int n = lin >> 5, f4 = lin & 31, k = f4 * 4;
        float4 v = ((const float4*)Wo)[lin];
        uint32_t h0 = pack_bf16x2(v.x, v.y);
        uint32_t h1 = pack_bf16x2(v.z, v.w);
        float fx = __uint_as_float(h0 << 16), fy = __uint_as_float(h0 & 0xffff0000u);
        float fz = __uint_as_float(h1 << 16), fw = __uint_as_float(h1 & 0xffff0000u);
        uint32_t l0 = pack_bf16x2(v.x - fx, v.y - fy);
        uint32_t l1 = pack_bf16x2(v.z - fz, v.w - fw);
        int kb = k >> 6;
        uint32_t off = (uint32_t)(kb * 16384 + n * 128 + (((k & 63) * 2) ^ ((n & 7) << 4)));
        *(uint2*)(g_Bo + off)         = make_uint2(h0, h1);
        *(uint2*)(g_Bo + 32768 + off) = make_uint2(l0, l1);
    }
}

// ---------------- Kernel 3: warp-MMA attention (R10 known-good) ------------
__global__ __launch_bounds__(256, 4) void k3_attn_tc(const float* __restrict__ adj) {
    extern __shared__ __align__(128) unsigned char dsm[];

    const int bh = blockIdx.y;
    const int i0 = blockIdx.x * MT;
    const int tid = threadIdx.x;
    const int warp = tid >> 5, lane = tid & 31;

    const uint32_t sb = (uint32_t)__cvta_generic_to_shared(dsm);
    const uint32_t sWhi_a = sb + SM_WHI;
    const uint32_t sWlo_a = sb + SM_WLO;
    const uint32_t sB_a   = sb + SM_SB;
    float* sh_rs  = (float*)(dsm + SM_RS);
    float* sh_rE  = (float*)(dsm + SM_RE);
    float* sh_rE5 = (float*)(dsm + SM_RE5);

    if (tid < MT) {
        int gi = bh * NN + i0 + tid;
        sh_rs [tid] = g_src[gi];
        sh_rE [tid] = g_E [gi];
        sh_rE5[tid] = g_E5[gi];
    }

    const int g0 = warp * 16;
    const int lr = lane & 7, lq = lane >> 3;
    const uint32_t xr = (uint32_t)lr << 4;

    const uint32_t a_rowoff = (uint32_t)(g0 + lr + ((lq & 1) << 3)) * 128u;
    const uint32_t a_cbx = (uint32_t)(lq >> 1) << 4;
    const uint32_t b_rowadd = (uint32_t)(lr + ((lq >> 1) << 3));
    const uint32_t b_cbx = (uint32_t)(lq & 1) << 4;

    float c[5][4];
    #pragma unroll
    for (int nt = 0; nt < 5; ++nt)
        #pragma unroll
        for (int q = 0; q < 4; ++q) c[nt][q] = 0.f;

    const int jo = bh * NN;
    const unsigned char* gB0 = g_B + (size_t)(bh * NTILES) * BTILE_BYTES;

    auto stage = [&](int buf, int t) {
        const unsigned char* gBt = gB0 + (size_t)t * BTILE_BYTES;
        const uint32_t dst = sB_a + (uint32_t)buf * BTILE_BYTES;
        #pragma unroll
        for (int i = 0; i < 3; ++i) {
            int idx = tid + 256 * i;
            if (idx < BTILE_BYTES / 16)
                cp16(dst + (uint32_t)idx * 16u, gBt + idx * 16);
        }
        asm volatile("cp.async.commit_group;");
    };

    stage(0, 0);

    for (int t = 0; t < NTILES; ++t) {
        asm volatile("cp.async.wait_group 0;");
        __syncthreads();

        if (t + 1 < NTILES) stage((t + 1) & 1, t + 1);

        {
            const int jt = t * KT;
            const int jg = jo + jt + 2 * lane;
            const float2 dv  = *(const float2*)&g_dst[jg];
            const float2 Fv  = *(const float2*)&g_F [jg];
            const float2 F5v = *(const float2*)&g_F5[jg];
            const float* arow = adj + (size_t)(i0 + g0) * NN + jt + 2 * lane;

            #pragma unroll
            for (int r = 0; r < 16; ++r) {
                const int m = g0 + r;
                const float rs_m  = sh_rs[m];
                const float rE_m  = sh_rE[m];
                const float rE5_m = sh_rE5[m];
                const float2 av = *(const float2*)(arow + (size_t)r * NN);

                float s0 = rs_m + dv.x;
                float c0 = (s0 > 0.f) ? rE_m * Fv.x : rE5_m * F5v.x;
                float w0 = c0 * av.x;
                float s1 = rs_m + dv.y;
                float c1 = (s1 > 0.f) ? rE_m * Fv.y : rE5_m * F5v.y;
                float w1 = c1 * av.y;

                uint32_t hw = pack_bf16x2(w0, w1);
                float f0 = __uint_as_float(hw << 16);
                float f1 = __uint_as_float(hw & 0xffff0000u);
                uint32_t lw = pack_bf16x2(w0 - f0, w1 - f1);

                uint32_t off = (uint32_t)(m * 128 + ((lane * 4) ^ ((m & 7) << 4)));
                asm volatile("st.shared.b32 [%0], %1;" :: "r"(sWhi_a + off), "r"(hw) : "memory");
                asm volatile("st.shared.b32 [%0], %1;" :: "r"(sWlo_a + off), "r"(lw) : "memory");
            }
        }
        __syncwarp();

        const uint32_t bb = sB_a + (uint32_t)(t & 1) * BTILE_BYTES;
        #pragma unroll
        for (int ch = 0; ch < 4; ++ch) {
            const uint32_t cba = (uint32_t)(ch * 32) + a_cbx;
            uint32_t ahi[4], alo[4];
            ldsm4(ahi, sWhi_a + a_rowoff + (cba ^ xr));
            ldsm4(alo, sWlo_a + a_rowoff + (cba ^ xr));
            const uint32_t cbb = (uint32_t)(ch * 32) + b_cbx;
            #pragma unroll
            for (int p = 0; p < 2; ++p) {
                const uint32_t baddr = bb + (uint32_t)(p * 16 + b_rowadd) * 128u + (cbb ^ xr);
                uint32_t bh4[4];
                ldsm4(bh4, baddr);
                mma_bf16(c[2 * p],     ahi, bh4[0], bh4[1]);
                mma_bf16(c[2 * p],     alo, bh4[0], bh4[1]);
                mma_bf16(c[2 * p + 1], ahi, bh4[2], bh4[3]);
                mma_bf16(c[2 * p + 1], alo, bh4[2], bh4[3]);
                uint32_t bl4[4];
                ldsm4(bl4, baddr + BSPLIT_BYTES);
                mma_bf16(c[2 * p],     ahi, bl4[0], bl4[1]);
                mma_bf16(c[2 * p + 1], ahi, bl4[2], bl4[3]);
            }
            const uint32_t baddr2 = bb + (uint32_t)(32 + lr) * 128u + (cbb ^ xr);
            uint32_t b2[2];
            ldsm2(b2, baddr2);
            mma_bf16(c[4], ahi, b2[0], b2[1]);
            mma_bf16(c[4], alo, b2[0], b2[1]);
        }
    }

    const float s_lo = __shfl_sync(0xffffffffu, c[4][0], lane & ~3);
    const float s_hi = __shfl_sync(0xffffffffu, c[4][2], lane & ~3);
    const float r0 = 1.0f / s_lo;
    const float r1 = 1.0f / s_hi;

    const int b = bh >> 2, hh = bh & 3;
    const int ia = i0 + g0 + (lane >> 2);
    float* dst0 = g_att + ((size_t)b * NN + ia) * DD + hh * DH + 2 * (lane & 3);
    float* dst1 = dst0 + 8 * (size_t)DD;
    #pragma unroll
    for (int nt = 0; nt < 4; ++nt) {
        *(float2*)(dst0 + nt * 8) = make_float2(c[nt][0] * r0, c[nt][1] * r0);
        *(float2*)(dst1 + nt * 8) = make_float2(c[nt][2] * r1, c[nt][3] * r1);
    }
}

// ---------------- Kernel 4a: warp-MMA out-proj + residual + LayerNorm ------
// grid 256 CTAs x 64 rows. Warp w = rg(w>>2: 32-row group) x cg(w&3: 32-col group).
// 3-term compensated bf16: A_hi*B_hi + A_lo*B_hi + A_hi*B_lo.
__global__ __launch_bounds__(256) void k4a_gemm_ln(const float* __restrict__ x,
                                                   const float* __restrict__ bo,
                                                   const float* __restrict__ gamma,
                                                   const float* __restrict__ beta,
                                                   float* __restrict__ out) {
    extern __shared__ __align__(128) unsigned char dsm[];

    const int tid = threadIdx.x;
    const int warp = tid >> 5, lane = tid & 31;
    const int r0 = blockIdx.x * 64;

    const uint32_t sb = (uint32_t)__cvta_generic_to_shared(dsm);
    const uint32_t sA = sb + K4_SM_A;          // hi; lo at +16384
    const uint32_t sB = sb + K4_SM_B;          // hi; lo at +32768
    float* yb  = (float*)(dsm + K4_SM_A);      // overlays A after MMA
    float* smu = (float*)(dsm + K4_SM_MU);
    float* srs = (float*)(dsm + K4_SM_RSD);

    // 1. stage Wo blob (64KB) via cp.async
    #pragma unroll
    for (int i = 0; i < 16; ++i) {
        int idx = tid + 256 * i;               // 4096 chunks
        cp16(sB + (uint32_t)idx * 16u, g_Bo + idx * 16);
    }
    asm volatile("cp.async.commit_group;");

    // 2. convert att rows -> bf16 hi/lo swizzled A tiles
    {
        const float4* att4 = (const float4*)(g_att + (size_t)r0 * DD);
        #pragma unroll
        for (int i = 0; i < 8; ++i) {
            int lin = tid + 256 * i;           // 2048 float4s (64 rows x 32/row)
            int m = lin >> 5, f4 = lin & 31, k = f4 * 4;
            float4 v = att4[lin];
            uint32_t h0 = pack_bf16x2(v.x, v.y);
            uint32_t h1 = pack_bf16x2(v.z, v.w);
            float fx = __uint_as_float(h0 << 16), fy = __uint_as_float(h0 & 0xffff0000u);
            float fz = __uint_as_float(h1 << 16), fw = __uint_as_float(h1 & 0xffff0000u);
            uint32_t l0 = pack_bf16x2(v.x - fx, v.y - fy);
            uint32_t l1 = pack_bf16x2(v.z - fz, v.w - fw);
            int kb = k >> 6;
            uint32_t off = (uint32_t)(kb * 8192 + m * 128 + (((k & 63) * 2) ^ ((m & 7) << 4)));
            asm volatile("st.shared.v2.b32 [%0], {%1,%2};" :: "r"(sA + off), "r"(h0), "r"(h1) : "memory");
            asm volatile("st.shared.v2.b32 [%0], {%1,%2};" :: "r"(sA + 16384u + off), "r"(l0), "r"(l1) : "memory");
        }
    }
    asm volatile("cp.async.wait_group 0;");
    __syncthreads();

    // 3. MMA: 8 k16-chunks; warp covers 32 rows x 32 cols
    const int rg = warp >> 2, cg = warp & 3;
    const int lr = lane & 7, lq = lane >> 3;
    const uint32_t xr = (uint32_t)lr << 4;
    const uint32_t a_rowpart = (uint32_t)(lr + ((lq & 1) << 3));
    const uint32_t a_cbx = (uint32_t)(lq >> 1) << 4;
    const uint32_t b_rowpart = (uint32_t)(lr + ((lq >> 1) << 3));
    const uint32_t b_cbx = (uint32_t)(lq & 1) << 4;

    float c[2][4][4];
    #pragma unroll
    for (int mt = 0; mt < 2; ++mt)
        #pragma unroll
        for (int nt = 0; nt < 4; ++nt)
            #pragma unroll
            for (int q = 0; q < 4; ++q) c[mt][nt][q] = 0.f;

    #pragma unroll
    for (int ch = 0; ch < 8; ++ch) {
        const int kb = ch >> 2, ck = ch & 3;
        const uint32_t colA = (uint32_t)(ck * 32) + a_cbx;
        const uint32_t colB = (uint32_t)(ck * 32) + b_cbx;
        uint32_t ah[2][4], al[2][4];
        #pragma unroll
        for (int mt = 0; mt < 2; ++mt) {
            uint32_t arow = (uint32_t)(rg * 32 + mt * 16) + a_rowpart;
            uint32_t aaddr = sA + (uint32_t)kb * 8192u + arow * 128u + (colA ^ xr);
            ldsm4(ah[mt], aaddr);
            ldsm4(al[mt], aaddr + 16384u);
        }
        #pragma unroll
        for (int p = 0; p < 2; ++p) {
            uint32_t brow = (uint32_t)(cg * 32 + p * 16) + b_rowpart;
            uint32_t baddr = sB + (uint32_t)kb * 16384u + brow * 128u + (colB ^ xr);
            uint32_t bh4[4], bl4[4];
            ldsm4(bh4, baddr);
            ldsm4(bl4, baddr + 32768u);
            #pragma unroll
            for (int mt = 0; mt < 2; ++mt) {
                mma_bf16(c[mt][2 * p],     ah[mt], bh4[0], bh4[1]);
                mma_bf16(c[mt][2 * p],     al[mt], bh4[0], bh4[1]);
                mma_bf16(c[mt][2 * p],     ah[mt], bl4[0], bl4[1]);
                mma_bf16(c[mt][2 * p + 1], ah[mt], bh4[2], bh4[3]);
                mma_bf16(c[mt][2 * p + 1], al[mt], bh4[2], bh4[3]);
                mma_bf16(c[mt][2 * p + 1], ah[mt], bl4[2], bl4[3]);
            }
        }
    }
    __syncthreads();   // all ldsm of A done; safe to overlay yb

    // 4. fragments -> yb (raw gemm result)
    #pragma unroll
    for (int mt = 0; mt < 2; ++mt) {
        #pragma unroll
        for (int nt = 0; nt < 4; ++nt) {
            int row = rg * 32 + mt * 16 + (lane >> 2);
            int col = cg * 32 + nt * 8 + (lane & 3) * 2;
            *(float2*)&yb[row * 128 + col]       = make_float2(c[mt][nt][0], c[mt][nt][1]);
            *(float2*)&yb[(row + 8) * 128 + col] = make_float2(c[mt][nt][2], c[mt][nt][3]);
        }
    }
    __syncthreads();

    // 5. stats pass: warp w -> rows 8w..8w+7. y = gemm + x + bo, writeback, reduce.
    {
        float bo4[4];
        #pragma unroll
        for (int cc = 0; cc < 4; ++cc) bo4[cc] = bo[lane + 32 * cc];
        #pragma unroll
        for (int rr = 0; rr < 8; ++rr) {
            int row = warp * 8 + rr;
            const float* xrow = x + (size_t)(r0 + row) * DD;
            float s = 0.f, q = 0.f, vv[4];
            #pragma unroll
            for (int cc = 0; cc < 4; ++cc) {
                int col = lane + 32 * cc;
                float v = yb[row * 128 + col] + xrow[col] + bo4[cc];
                vv[cc] = v;
                s += v;
                q += v * v;
            }
            #pragma unroll
            for (int cc = 0; cc < 4; ++cc) yb[row * 128 + lane + 32 * cc] = vv[cc];
            #pragma unroll
            for (int off = 16; off > 0; off >>= 1) {
                s += __shfl_xor_sync(0xffffffffu, s, off);
                q += __shfl_xor_sync(0xffffffffu, q, off);
            }
            if (lane == 0) {
                float mu = s * (1.0f / DD);
                float var = q * (1.0f / DD) - mu * mu;
                smu[row] = mu;
                srs[row] = rsqrtf(var + 1e-5f);
            }
        }
    }
    __syncthreads();

    // 6. normalized coalesced store
    #pragma unroll
    for (int i = 0; i < 8; ++i) {
        int lin = tid + 256 * i;               // 2048 float4s
        int m = lin >> 5, f4 = lin & 31, col = f4 * 4;
        float4 v = *(float4*)&yb[m * 128 + col];
        float4 g = *(const float4*)&gamma[col];
        float4 be = *(const float4*)&beta[col];
        float mu = smu[m], rs = srs[m];
        float4 o;
        o.x = (v.x - mu) * rs * g.x + be.x;
        o.y = (v.y - mu) * rs * g.y + be.y;
        o.z = (v.z - mu) * rs * g.z + be.z;
        o.w = (v.w - mu) * rs * g.w + be.w;
        *(float4*)&out[(size_t)(r0 + m) * DD + col] = o;
    }
}

// ---------------- launch ----------------
extern "C" void kernel_launch(void* const* d_in, const int* in_sizes, int n_in,
                              void* d_out, int out_size) {
    const float* x     = (const float*)d_in[0];
    const float* adj   = (const float*)d_in[1];
    const float* W     = (const float*)d_in[2];
    const float* a_src = (const float*)d_in[3];
    const float* a_dst = (const float*)d_in[4];
    const float* Wo    = (const float*)d_in[5];
    const float* bo    = (const float*)d_in[6];
    const float* gamma = (const float*)d_in[7];
    const float* beta  = (const float*)d_in[8];
    float* out = (float*)d_out;

    cudaFuncSetAttribute(k3_attn_tc, cudaFuncAttributeMaxDynamicSharedMemorySize, SM_TOTAL);
    cudaFuncSetAttribute(k4a_gemm_ln, cudaFuncAttributeMaxDynamicSharedMemorySize, K4_SM_TOT);

    k1_proj<<<BN / 16, 128>>>(x, W);
    k2c_wo<<<1, 256>>>(Wo);
    k2_srcdst<<<(NBH * NN) / 256, 256>>>(a_src, a_dst);
    k2b_btiles<<<dim3(NTILES, NBH), 128>>>();
    k3_attn_tc<<<dim3(NN / MT, NBH), 256, SM_TOTAL>>>(adj);
    k4a_gemm_ln<<<BN / 64, 256, K4_SM_TOT>>>(x, bo, gamma, beta, out);
}